// round 10
// baseline (speedup 1.0000x reference)
#include <cuda_runtime.h>
#include <cuda_bf16.h>
#include <math.h>
#include <stdint.h>

// Problem constants
#define HIDDEN 2048
#define NHEAD  16
#define HDIM   128
#define BB     2
#define SSEQ   2048
#define BH     (BB * NHEAD)      // 32
#define MROWS  (BB * SSEQ)       // 4096

// ---------------- scratch (device globals; no allocation allowed) -----------
__device__ __align__(128) __nv_bfloat16 g_xh [(size_t)MROWS * HIDDEN];
__device__ __align__(128) __nv_bfloat16 g_xl [(size_t)MROWS * HIDDEN];
__device__ __align__(128) __nv_bfloat16 g_w3h[(size_t)3 * HIDDEN * HIDDEN];  // Wq|Wk|Wv
__device__ __align__(128) __nv_bfloat16 g_w3l[(size_t)3 * HIDDEN * HIDDEN];
__device__ __align__(128) __nv_bfloat16 g_woh[(size_t)HIDDEN * HIDDEN];
__device__ __align__(128) __nv_bfloat16 g_wol[(size_t)HIDDEN * HIDDEN];
__device__ __align__(128) float         g_b3 [3 * HIDDEN];                   // bq|bk|bv
__device__ __align__(128) __nv_bfloat16 g_qh [(size_t)BH * SSEQ * HDIM];  // [B,H,S,D]
__device__ __align__(128) __nv_bfloat16 g_ql [(size_t)BH * SSEQ * HDIM];
__device__ __align__(128) __nv_bfloat16 g_kh [(size_t)BH * SSEQ * HDIM];
__device__ __align__(128) __nv_bfloat16 g_kl [(size_t)BH * SSEQ * HDIM];
__device__ __align__(128) __nv_bfloat16 g_vh [(size_t)BH * SSEQ * HDIM];
__device__ __align__(128) __nv_bfloat16 g_vl [(size_t)BH * SSEQ * HDIM];
__device__ __align__(128) __nv_bfloat16 g_aoh[(size_t)MROWS * HIDDEN];
__device__ __align__(128) __nv_bfloat16 g_aol[(size_t)MROWS * HIDDEN];

// ============================ PTX helpers ====================================
__device__ __forceinline__ uint32_t smem_to_u32(const void* smem_ptr) {
    uint32_t addr;
    asm("{ .reg .u64 tmp; cvta.to.shared.u64 tmp, %1; cvt.u32.u64 %0, tmp; }"
        : "=r"(addr) : "l"(smem_ptr));
    return addr;
}
#define CP_ASYNC16(smem_u32, gptr) \
    asm volatile("cp.async.cg.shared.global [%0], [%1], 16;" \
        :: "r"((uint32_t)(smem_u32)), "l"(gptr) : "memory")
#define CP_ASYNC_COMMIT() asm volatile("cp.async.commit_group;" ::: "memory")
#define CP_ASYNC_WAIT(n)  asm volatile("cp.async.wait_group %0;" :: "n"(n) : "memory")

__device__ __forceinline__ void ldsm4(uint32_t* r, uint32_t addr) {
    asm volatile("ldmatrix.sync.aligned.m8n8.x4.shared.b16 {%0,%1,%2,%3}, [%4];"
        : "=r"(r[0]), "=r"(r[1]), "=r"(r[2]), "=r"(r[3]) : "r"(addr));
}
__device__ __forceinline__ void ldsm4t(uint32_t* r, uint32_t addr) {
    asm volatile("ldmatrix.sync.aligned.m8n8.x4.trans.shared.b16 {%0,%1,%2,%3}, [%4];"
        : "=r"(r[0]), "=r"(r[1]), "=r"(r[2]), "=r"(r[3]) : "r"(addr));
}
__device__ __forceinline__ void mma16816(float* d, const uint32_t* a,
                                         uint32_t b0, uint32_t b1) {
    asm volatile(
        "mma.sync.aligned.m16n8k16.row.col.f32.bf16.bf16.f32 "
        "{%0,%1,%2,%3}, {%4,%5,%6,%7}, {%8,%9}, {%0,%1,%2,%3};"
        : "+f"(d[0]), "+f"(d[1]), "+f"(d[2]), "+f"(d[3])
        : "r"(a[0]), "r"(a[1]), "r"(a[2]), "r"(a[3]), "r"(b0), "r"(b1));
}
__device__ __forceinline__ float fast_exp2(float x) {
    float y;
    asm("ex2.approx.f32 %0, %1;" : "=f"(y) : "f"(x));
    return y;
}

// ===================== HMMA bf16x3 NT GEMM ==================================
// (unchanged from round 9: 128x128 CTA, K-chunk 32, XOR swizzle, 3-stage,
//  single sync, 2 CTAs/SM)
#define TG_TILE     (128 * 64)              // 8192
#define TG_STAGE    (4 * TG_TILE)           // Ah, Al, Bh, Bl = 32768
#define TG_SMEM     (3 * TG_STAGE)          // 98304 -> 2 CTAs/SM

__global__ void __launch_bounds__(256, 2)
tgemm_nt(const __nv_bfloat16* __restrict__ Ah, const __nv_bfloat16* __restrict__ Al,
         const __nv_bfloat16* __restrict__ Bh, const __nv_bfloat16* __restrict__ Bl,
         const float* __restrict__ bias, int K, int Ntot, int mode,
         float* __restrict__ outF,
         __nv_bfloat16* __restrict__ o0h, __nv_bfloat16* __restrict__ o0l,
         __nv_bfloat16* __restrict__ o1h, __nv_bfloat16* __restrict__ o1l,
         __nv_bfloat16* __restrict__ o2h, __nv_bfloat16* __restrict__ o2l)
{
    extern __shared__ __align__(128) char smem[];
    const uint32_t sb = smem_to_u32(smem);

    const int tid  = threadIdx.x;
    const int lane = tid & 31;
    const int wid  = tid >> 5;
    const int wm   = wid >> 2;
    const int wn   = wid & 3;

    const int m0 = blockIdx.y * 128;
    const int n0 = blockIdx.x * 128;
    const int nch = K >> 5;                  // K / 32

    const size_t aBase = (size_t)m0 * K;
    const size_t bBase = (size_t)n0 * K;

    float acc[4][4][4];
    #pragma unroll
    for (int i = 0; i < 4; i++)
        #pragma unroll
        for (int j = 0; j < 4; j++)
            #pragma unroll
            for (int t = 0; t < 4; t++) acc[i][j][t] = 0.0f;

    auto load_chunk = [&](int buf, int k0) {
        const uint32_t tb = sb + buf * TG_STAGE;
        #pragma unroll
        for (int ii = 0; ii < 2; ii++) {
            const int i = tid + ii * 256;        // 0..511
            const int r = i >> 2;                // row 0..127
            const int c = i & 3;                 // 16B chunk 0..3
            const uint32_t so = (uint32_t)(r * 64 + ((c ^ ((r >> 1) & 3)) << 4));
            const size_t aOff = aBase + (size_t)r * K + k0 + c * 8;
            const size_t bOff = bBase + (size_t)r * K + k0 + c * 8;
            CP_ASYNC16(tb + 0 * TG_TILE + so, (const char*)(Ah + aOff));
            CP_ASYNC16(tb + 1 * TG_TILE + so, (const char*)(Al + aOff));
            CP_ASYNC16(tb + 2 * TG_TILE + so, (const char*)(Bh + bOff));
            CP_ASYNC16(tb + 3 * TG_TILE + so, (const char*)(Bl + bOff));
        }
        CP_ASYNC_COMMIT();
    };

    const int hiA = lane >> 4;
    const int swA = ((lane & 15) >> 1) & 3;
    const uint32_t aRowOff = (uint32_t)((wm * 64 + (lane & 15)) * 64);
    const int hiB = (lane >> 3) & 1;
    const int swB = ((lane & 7) >> 1) & 3;
    const uint32_t bRowOff = (uint32_t)((wn * 32 + (lane & 7) + ((lane >> 4) & 1) * 8) * 64);

    load_chunk(0, 0);
    if (nch > 1) load_chunk(1, 32);

    for (int c = 0; c < nch; c++) {
        const int buf = c % 3;
        if (c + 1 < nch) { CP_ASYNC_WAIT(1); } else { CP_ASYNC_WAIT(0); }
        __syncthreads();
        if (c + 2 < nch) load_chunk((c + 2) % 3, (c + 2) * 32);

        const uint32_t tb  = sb + buf * TG_STAGE;
        const uint32_t tAh = tb + 0 * TG_TILE + aRowOff;
        const uint32_t tAl = tb + 1 * TG_TILE + aRowOff;
        const uint32_t tBh = tb + 2 * TG_TILE + bRowOff;
        const uint32_t tBl = tb + 3 * TG_TILE + bRowOff;

        #pragma unroll
        for (int ks = 0; ks < 2; ks++) {
            const uint32_t koA = (uint32_t)(((ks * 2 + hiA) ^ swA) << 4);
            const uint32_t koB = (uint32_t)(((ks * 2 + hiB) ^ swB) << 4);
            uint32_t a[4][4], bh[2][4], bl[2][4];
            #pragma unroll
            for (int mt = 0; mt < 4; mt++) ldsm4(a[mt], tAh + mt * (16 * 64) + koA);
            #pragma unroll
            for (int nt = 0; nt < 2; nt++) {
                ldsm4(bh[nt], tBh + nt * (16 * 64) + koB);
                ldsm4(bl[nt], tBl + nt * (16 * 64) + koB);
            }
            #pragma unroll
            for (int mi = 0; mi < 4; mi++)
                #pragma unroll
                for (int ni = 0; ni < 4; ni++) {
                    const int g = ni >> 1, o = (ni & 1) * 2;
                    mma16816(acc[mi][ni], a[mi], bh[g][o], bh[g][o + 1]);  // Ah*Bh
                    mma16816(acc[mi][ni], a[mi], bl[g][o], bl[g][o + 1]);  // Ah*Bl
                }
            #pragma unroll
            for (int mt = 0; mt < 4; mt++) ldsm4(a[mt], tAl + mt * (16 * 64) + koA);
            #pragma unroll
            for (int mi = 0; mi < 4; mi++)
                #pragma unroll
                for (int ni = 0; ni < 4; ni++) {
                    const int g = ni >> 1, o = (ni & 1) * 2;
                    mma16816(acc[mi][ni], a[mi], bh[g][o], bh[g][o + 1]);  // Al*Bh
                }
        }
    }

    const int gid = lane >> 2;
    const int tig = lane & 3;

    auto storePair = [&](int m, int n, float v0, float v1) {
        if (bias) { v0 += bias[n]; v1 += bias[n + 1]; }
        if (mode == 0) {
            float2 t; t.x = v0; t.y = v1;
            *reinterpret_cast<float2*>(&outF[(size_t)m * Ntot + n]) = t;
        } else {
            __nv_bfloat16 h0 = __float2bfloat16(v0);
            __nv_bfloat16 l0 = __float2bfloat16(v0 - __bfloat162float(h0));
            __nv_bfloat16 h1 = __float2bfloat16(v1);
            __nv_bfloat16 l1 = __float2bfloat16(v1 - __bfloat162float(h1));
            const int p  = n >> 11;                 // 0=q, 1=k, 2=v
            const int n2 = n & (HIDDEN - 1);
            const int b = m >> 11, s = m & (SSEQ - 1);
            const int h = n2 >> 7, d = n2 & (HDIM - 1);
            __nv_bfloat16* oh = (p == 0) ? o0h : ((p == 1) ? o1h : o2h);
            __nv_bfloat16* ol = (p == 0) ? o0l : ((p == 1) ? o1l : o2l);
            const size_t idx = (((size_t)(b * NHEAD + h) * SSEQ) + s) * HDIM + d;
            __nv_bfloat162 th; th.x = h0; th.y = h1;
            __nv_bfloat162 tl; tl.x = l0; tl.y = l1;
            *reinterpret_cast<__nv_bfloat162*>(&oh[idx]) = th;
            *reinterpret_cast<__nv_bfloat162*>(&ol[idx]) = tl;
        }
    };

    #pragma unroll
    for (int mi = 0; mi < 4; mi++) {
        #pragma unroll
        for (int ni = 0; ni < 4; ni++) {
            const int m = m0 + wm * 64 + mi * 16 + gid;
            const int n = n0 + wn * 32 + ni * 8 + tig * 2;
            storePair(m,     n, acc[mi][ni][0], acc[mi][ni][1]);
            storePair(m + 8, n, acc[mi][ni][2], acc[mi][ni][3]);
        }
    }
}

// ===================== fused flash attention (bf16x3) =======================
// 64 q-rows/CTA, 128 thr, 32-key stages, 3 stages, 2 CTAs/SM.
// Software-pipelined: S(c+1) MMAs issued BEFORE softmax(c)+PV(c) so the
// tensor pipe stays busy through the softmax chain.  Ping-pong S buffers.
// K and V use separate cp.async commit groups (K released earlier).
#define FA_STRIDE  272                       // 128 bf16 + 8 pad
#define FA_KVTILE  (32 * FA_STRIDE)          // 8704
#define FA_STAGE   (4 * FA_KVTILE)           // Kh,Kl,Vh,Vl = 34816
#define FA_SMEM    (3 * FA_STAGE)            // 104448 -> 2 CTAs/SM
#define FA_QTILE   (64 * FA_STRIDE)          // 17408

__global__ void __launch_bounds__(128, 2)
fa_kernel(const __nv_bfloat16* __restrict__ qh, const __nv_bfloat16* __restrict__ ql,
          const __nv_bfloat16* __restrict__ kh, const __nv_bfloat16* __restrict__ kl,
          const __nv_bfloat16* __restrict__ vh, const __nv_bfloat16* __restrict__ vl,
          const float* __restrict__ mask,
          __nv_bfloat16* __restrict__ aoh, __nv_bfloat16* __restrict__ aol)
{
    extern __shared__ __align__(128) char smem[];
    const uint32_t sb   = smem_to_u32(smem);
    const uint32_t sStg = sb;

    const int tid  = threadIdx.x;
    const int lane = tid & 31;
    const int wid  = tid >> 5;           // 0..3
    const int gid  = lane >> 2;
    const int tig  = lane & 3;

    const int z  = blockIdx.y;
    const int q0 = blockIdx.x * 64;
    const int b  = z >> 4;
    const int h  = z & (NHEAD - 1);

    const size_t qBase  = ((size_t)z * SSEQ + q0) * HDIM;
    const size_t kvBase = (size_t)z * SSEQ * HDIM;

    // ---- Q tile (64 rows) staged into stage-2 area, later moved to regs
    const uint32_t sQh = sStg + 2 * FA_STAGE;
    const uint32_t sQl = sQh + FA_QTILE;
    #pragma unroll
    for (int ii = 0; ii < 8; ii++) {
        const int i = tid + ii * 128;
        const int r = i >> 4;
        const int c = i & 15;
        const uint32_t so = (uint32_t)(r * FA_STRIDE + c * 16);
        const size_t go = qBase + (size_t)r * HDIM + c * 8;
        CP_ASYNC16(sQh + so, (const char*)(qh + go));
        CP_ASYNC16(sQl + so, (const char*)(ql + go));
    }
    CP_ASYNC_COMMIT();                       // group: Q

    auto load_k = [&](int st, int k0) {
        const uint32_t tb = sStg + st * FA_STAGE;
        #pragma unroll
        for (int ii = 0; ii < 4; ii++) {
            const int i = tid + ii * 128;
            const int r = i >> 4;
            const int c = i & 15;
            const uint32_t so = (uint32_t)(r * FA_STRIDE + c * 16);
            const size_t go = kvBase + (size_t)(k0 + r) * HDIM + c * 8;
            CP_ASYNC16(tb + 0 * FA_KVTILE + so, (const char*)(kh + go));
            CP_ASYNC16(tb + 1 * FA_KVTILE + so, (const char*)(kl + go));
        }
        CP_ASYNC_COMMIT();
    };
    auto load_v = [&](int st, int k0) {
        const uint32_t tb = sStg + st * FA_STAGE;
        #pragma unroll
        for (int ii = 0; ii < 4; ii++) {
            const int i = tid + ii * 128;
            const int r = i >> 4;
            const int c = i & 15;
            const uint32_t so = (uint32_t)(r * FA_STRIDE + c * 16);
            const size_t go = kvBase + (size_t)(k0 + r) * HDIM + c * 8;
            CP_ASYNC16(tb + 2 * FA_KVTILE + so, (const char*)(vh + go));
            CP_ASYNC16(tb + 3 * FA_KVTILE + so, (const char*)(vl + go));
        }
        CP_ASYNC_COMMIT();
    };
    load_k(0, 0);  load_v(0, 0);             // groups: K0, V0
    load_k(1, 32); load_v(1, 32);            // groups: K1, V1

    // Q fragments -> registers (Q, K0, V0 complete; K1, V1 may pend)
    const uint32_t aOff = (uint32_t)((16 * wid + (lane & 15)) * FA_STRIDE + (lane >> 4) * 16);
    uint32_t qA[8][4], qL[8][4];
    CP_ASYNC_WAIT(2);
    __syncthreads();
    #pragma unroll
    for (int kd = 0; kd < 8; kd++) {
        ldsm4(qA[kd], sQh + aOff + kd * 32);
        ldsm4(qL[kd], sQl + aOff + kd * 32);
    }

    float O[16][4];
    #pragma unroll
    for (int i = 0; i < 16; i++)
        #pragma unroll
        for (int j = 0; j < 4; j++) O[i][j] = 0.0f;
    float m0 = -1e30f, m1 = -1e30f, l0 = 0.0f, l1 = 0.0f;

    const uint32_t bOff = (uint32_t)(((lane & 7) + ((lane >> 4) & 1) * 8) * FA_STRIDE
                                     + ((lane >> 3) & 1) * 16);
    const uint32_t vOff = (uint32_t)(((lane & 7) + ((lane >> 3) & 1) * 8) * FA_STRIDE
                                     + ((lane >> 4) & 1) * 16);
    const float* mrow = mask + (size_t)b * SSEQ;
    const float LOG2E  = 1.4426950408889634f;
    const float scale2 = 0.08838834764831845f * LOG2E;   // (1/sqrt(128))*log2(e)

    // S = Q @ K(stage)^T  (bf16x3)
    auto smma = [&](int stage, float (&S)[4][4]) {
        const uint32_t tb = sStg + (uint32_t)stage * FA_STAGE;
        #pragma unroll
        for (int i = 0; i < 4; i++)
            #pragma unroll
            for (int j = 0; j < 4; j++) S[i][j] = 0.0f;
        #pragma unroll
        for (int kd = 0; kd < 8; kd++) {
            #pragma unroll
            for (int np = 0; np < 2; np++) {
                uint32_t bH[4], bL[4];
                ldsm4(bH, tb + 0 * FA_KVTILE + bOff + np * (16 * FA_STRIDE) + kd * 32);
                ldsm4(bL, tb + 1 * FA_KVTILE + bOff + np * (16 * FA_STRIDE) + kd * 32);
                mma16816(S[2 * np],     qA[kd], bH[0], bH[1]);
                mma16816(S[2 * np],     qL[kd], bH[0], bH[1]);
                mma16816(S[2 * np],     qA[kd], bL[0], bL[1]);
                mma16816(S[2 * np + 1], qA[kd], bH[2], bH[3]);
                mma16816(S[2 * np + 1], qL[kd], bH[2], bH[3]);
                mma16816(S[2 * np + 1], qA[kd], bL[2], bL[3]);
            }
        }
    };

    // one pipelined iteration: consume Scur (chunk c), produce Snext (chunk c+1)
    auto body = [&](int c, float (&Scur)[4][4], float (&Snext)[4][4]) {
        if (c + 2 < 64) { CP_ASYNC_WAIT(1); } else { CP_ASYNC_WAIT(0); }
        __syncthreads();
        if (c + 2 < 64) {
            load_k((c + 2) % 3, (c + 2) * 32);
            load_v((c + 2) % 3, (c + 2) * 32);
        }
        if (c + 1 < 64) smma((c + 1) % 3, Snext);   // tensor work covering softmax

        const int k0 = c * 32;
        const uint32_t tb = sStg + (uint32_t)(c % 3) * FA_STAGE;

        // ---- scale + mask (log2 domain) on Scur
        #pragma unroll
        for (int nt = 0; nt < 4; nt++) {
            const float2 mv = *reinterpret_cast<const float2*>(mrow + k0 + nt * 8 + 2 * tig);
            const float mx2 = mv.x * LOG2E;
            const float my2 = mv.y * LOG2E;
            Scur[nt][0] = fmaf(Scur[nt][0], scale2, mx2);
            Scur[nt][1] = fmaf(Scur[nt][1], scale2, my2);
            Scur[nt][2] = fmaf(Scur[nt][2], scale2, mx2);
            Scur[nt][3] = fmaf(Scur[nt][3], scale2, my2);
        }

        float mx0 = -1e30f, mx1 = -1e30f;
        #pragma unroll
        for (int nt = 0; nt < 4; nt++) {
            mx0 = fmaxf(mx0, fmaxf(Scur[nt][0], Scur[nt][1]));
            mx1 = fmaxf(mx1, fmaxf(Scur[nt][2], Scur[nt][3]));
        }
        mx0 = fmaxf(mx0, __shfl_xor_sync(0xFFFFFFFFu, mx0, 1));
        mx0 = fmaxf(mx0, __shfl_xor_sync(0xFFFFFFFFu, mx0, 2));
        mx1 = fmaxf(mx1, __shfl_xor_sync(0xFFFFFFFFu, mx1, 1));
        mx1 = fmaxf(mx1, __shfl_xor_sync(0xFFFFFFFFu, mx1, 2));

        const float nm0 = fmaxf(m0, mx0);
        const float nm1 = fmaxf(m1, mx1);
        const float ef0 = fast_exp2(m0 - nm0);
        const float ef1 = fast_exp2(m1 - nm1);

        float rs0 = 0.0f, rs1 = 0.0f;
        #pragma unroll
        for (int nt = 0; nt < 4; nt++) {
            Scur[nt][0] = fast_exp2(Scur[nt][0] - nm0);
            Scur[nt][1] = fast_exp2(Scur[nt][1] - nm0);
            Scur[nt][2] = fast_exp2(Scur[nt][2] - nm1);
            Scur[nt][3] = fast_exp2(Scur[nt][3] - nm1);
            rs0 += Scur[nt][0] + Scur[nt][1];
            rs1 += Scur[nt][2] + Scur[nt][3];
        }
        rs0 += __shfl_xor_sync(0xFFFFFFFFu, rs0, 1);
        rs0 += __shfl_xor_sync(0xFFFFFFFFu, rs0, 2);
        rs1 += __shfl_xor_sync(0xFFFFFFFFu, rs1, 1);
        rs1 += __shfl_xor_sync(0xFFFFFFFFu, rs1, 2);

        l0 = l0 * ef0 + rs0;
        l1 = l1 * ef1 + rs1;
        m0 = nm0; m1 = nm1;

        #pragma unroll
        for (int nt = 0; nt < 16; nt++) {
            O[nt][0] *= ef0; O[nt][1] *= ef0;
            O[nt][2] *= ef1; O[nt][3] *= ef1;
        }

        // ---- P (hi/lo) @ V(c)
        #pragma unroll
        for (int ks = 0; ks < 2; ks++) {
            uint32_t paH[4], paL[4];
            #pragma unroll
            for (int q = 0; q < 2; q++) {
                const float* s4 = Scur[2 * ks + q];
                #pragma unroll
                for (int rr = 0; rr < 2; rr++) {
                    const float x = s4[rr * 2 + 0];
                    const float y = s4[rr * 2 + 1];
                    const __nv_bfloat16 hx = __float2bfloat16(x);
                    const __nv_bfloat16 hy = __float2bfloat16(y);
                    __nv_bfloat162 th; th.x = hx; th.y = hy;
                    __nv_bfloat162 tl;
                    tl.x = __float2bfloat16(x - __bfloat162float(hx));
                    tl.y = __float2bfloat16(y - __bfloat162float(hy));
                    paH[q * 2 + rr] = *reinterpret_cast<uint32_t*>(&th);
                    paL[q * 2 + rr] = *reinterpret_cast<uint32_t*>(&tl);
                }
            }
            #pragma unroll
            for (int ntp = 0; ntp < 8; ntp++) {
                uint32_t vH[4], vL[4];
                ldsm4t(vH, tb + 2 * FA_KVTILE + vOff + ks * (16 * FA_STRIDE) + ntp * 32);
                ldsm4t(vL, tb + 3 * FA_KVTILE + vOff + ks * (16 * FA_STRIDE) + ntp * 32);
                mma16816(O[2 * ntp],     paH, vH[0], vH[1]);
                mma16816(O[2 * ntp],     paL, vH[0], vH[1]);
                mma16816(O[2 * ntp],     paH, vL[0], vL[1]);
                mma16816(O[2 * ntp + 1], paH, vH[2], vH[3]);
                mma16816(O[2 * ntp + 1], paL, vH[2], vH[3]);
                mma16816(O[2 * ntp + 1], paH, vL[2], vL[3]);
            }
        }
    };

    // prologue: S(0) into SA (stage 0 K is ready)
    float SA[4][4], SB[4][4];
    smma(0, SA);

    for (int cc = 0; cc < 64; cc += 2) {
        body(cc,     SA, SB);
        body(cc + 1, SB, SA);
    }

    const float inv0 = 1.0f / l0;
    const float inv1 = 1.0f / l1;
    const int r0 = q0 + 16 * wid + gid;
    const int r1 = r0 + 8;
    #pragma unroll
    for (int nt = 0; nt < 16; nt++) {
        const int d = h * HDIM + nt * 8 + 2 * tig;
        const size_t i0 = ((size_t)b * SSEQ + r0) * HIDDEN + d;
        const size_t i1 = ((size_t)b * SSEQ + r1) * HIDDEN + d;
        const float v00 = O[nt][0] * inv0, v01 = O[nt][1] * inv0;
        const float v10 = O[nt][2] * inv1, v11 = O[nt][3] * inv1;

        const __nv_bfloat16 h00 = __float2bfloat16(v00);
        const __nv_bfloat16 h01 = __float2bfloat16(v01);
        const __nv_bfloat16 h10 = __float2bfloat16(v10);
        const __nv_bfloat16 h11 = __float2bfloat16(v11);
        __nv_bfloat162 th0; th0.x = h00; th0.y = h01;
        __nv_bfloat162 th1; th1.x = h10; th1.y = h11;
        __nv_bfloat162 tl0;
        tl0.x = __float2bfloat16(v00 - __bfloat162float(h00));
        tl0.y = __float2bfloat16(v01 - __bfloat162float(h01));
        __nv_bfloat162 tl1;
        tl1.x = __float2bfloat16(v10 - __bfloat162float(h10));
        tl1.y = __float2bfloat16(v11 - __bfloat162float(h11));
        *reinterpret_cast<__nv_bfloat162*>(&aoh[i0]) = th0;
        *reinterpret_cast<__nv_bfloat162*>(&aol[i0]) = tl0;
        *reinterpret_cast<__nv_bfloat162*>(&aoh[i1]) = th1;
        *reinterpret_cast<__nv_bfloat162*>(&aol[i1]) = tl1;
    }
}

// ===================== fp32 -> bf16 hi/lo split =============================
__global__ void __launch_bounds__(256)
split_bf16(const float* __restrict__ in, __nv_bfloat16* __restrict__ hi,
           __nv_bfloat16* __restrict__ lo, int n4)
{
    const int i = blockIdx.x * 256 + threadIdx.x;
    if (i >= n4) return;
    const float4 v = reinterpret_cast<const float4*>(in)[i];
    union { __nv_bfloat16 b[4]; uint2 u; } H, L;
    H.b[0] = __float2bfloat16(v.x);
    H.b[1] = __float2bfloat16(v.y);
    H.b[2] = __float2bfloat16(v.z);
    H.b[3] = __float2bfloat16(v.w);
    L.b[0] = __float2bfloat16(v.x - __bfloat162float(H.b[0]));
    L.b[1] = __float2bfloat16(v.y - __bfloat162float(H.b[1]));
    L.b[2] = __float2bfloat16(v.z - __bfloat162float(H.b[2]));
    L.b[3] = __float2bfloat16(v.w - __bfloat162float(H.b[3]));
    reinterpret_cast<uint2*>(hi)[i] = H.u;
    reinterpret_cast<uint2*>(lo)[i] = L.u;
}

// 4 weight matrices in one launch: blockIdx.y selects Wq/Wk/Wv/Wo.
__global__ void __launch_bounds__(256)
split_bf16_w4(const float* __restrict__ w0, const float* __restrict__ w1,
              const float* __restrict__ w2, const float* __restrict__ w3,
              __nv_bfloat16* __restrict__ w3h, __nv_bfloat16* __restrict__ w3l,
              __nv_bfloat16* __restrict__ woh, __nv_bfloat16* __restrict__ wol,
              int n4)
{
    const int i = blockIdx.x * 256 + threadIdx.x;
    if (i >= n4) return;
    const int p = blockIdx.y;
    const float* in = (p == 0) ? w0 : (p == 1) ? w1 : (p == 2) ? w2 : w3;
    const size_t wOff = (size_t)HIDDEN * HIDDEN / 4;   // in uint2 units
    __nv_bfloat16* hi;
    __nv_bfloat16* lo;
    size_t o;
    if (p < 3) { hi = w3h; lo = w3l; o = (size_t)p * wOff; }
    else       { hi = woh; lo = wol; o = 0; }

    const float4 v = reinterpret_cast<const float4*>(in)[i];
    union { __nv_bfloat16 b[4]; uint2 u; } H, L;
    H.b[0] = __float2bfloat16(v.x);
    H.b[1] = __float2bfloat16(v.y);
    H.b[2] = __float2bfloat16(v.z);
    H.b[3] = __float2bfloat16(v.w);
    L.b[0] = __float2bfloat16(v.x - __bfloat162float(H.b[0]));
    L.b[1] = __float2bfloat16(v.y - __bfloat162float(H.b[1]));
    L.b[2] = __float2bfloat16(v.z - __bfloat162float(H.b[2]));
    L.b[3] = __float2bfloat16(v.w - __bfloat162float(H.b[3]));
    reinterpret_cast<uint2*>(hi)[o + i] = H.u;
    reinterpret_cast<uint2*>(lo)[o + i] = L.u;
}

// bias concat: [bq | bk | bv]
__global__ void __launch_bounds__(256)
concat_bias(const float* __restrict__ a, const float* __restrict__ b,
            const float* __restrict__ c, float* __restrict__ o)
{
    const int i = blockIdx.x * 256 + threadIdx.x;
    if (i < HIDDEN)          o[i] = a[i];
    else if (i < 2 * HIDDEN) o[i] = b[i - HIDDEN];
    else if (i < 3 * HIDDEN) o[i] = c[i - 2 * HIDDEN];
}

// ---------------------------------------------------------------------------
extern "C" void kernel_launch(void* const* d_in, const int* in_sizes, int n_in,
                              void* d_out, int out_size)
{
    (void)in_sizes; (void)n_in; (void)out_size;
    const float* x    = (const float*)d_in[0];
    const float* mask = (const float*)d_in[1];
    const float* Wq   = (const float*)d_in[2];
    const float* bq   = (const float*)d_in[3];
    const float* Wk   = (const float*)d_in[4];
    const float* bk   = (const float*)d_in[5];
    const float* Wv   = (const float*)d_in[6];
    const float* bv   = (const float*)d_in[7];
    const float* Wo   = (const float*)d_in[8];
    const float* bo   = (const float*)d_in[9];
    float* out = (float*)d_out;

    __nv_bfloat16 *xh, *xl, *w3h, *w3l, *woh, *wol;
    __nv_bfloat16 *qh, *ql, *kh, *kl, *vh, *vl, *aoh, *aol;
    float* b3;
    cudaGetSymbolAddress((void**)&xh,  g_xh);
    cudaGetSymbolAddress((void**)&xl,  g_xl);
    cudaGetSymbolAddress((void**)&w3h, g_w3h);
    cudaGetSymbolAddress((void**)&w3l, g_w3l);
    cudaGetSymbolAddress((void**)&woh, g_woh);
    cudaGetSymbolAddress((void**)&wol, g_wol);
    cudaGetSymbolAddress((void**)&b3,  g_b3);
    cudaGetSymbolAddress((void**)&qh,  g_qh);
    cudaGetSymbolAddress((void**)&ql,  g_ql);
    cudaGetSymbolAddress((void**)&kh,  g_kh);
    cudaGetSymbolAddress((void**)&kl,  g_kl);
    cudaGetSymbolAddress((void**)&vh,  g_vh);
    cudaGetSymbolAddress((void**)&vl,  g_vl);
    cudaGetSymbolAddress((void**)&aoh, g_aoh);
    cudaGetSymbolAddress((void**)&aol, g_aol);

    cudaFuncSetAttribute(tgemm_nt, cudaFuncAttributeMaxDynamicSharedMemorySize,
                         TG_SMEM);
    cudaFuncSetAttribute(fa_kernel, cudaFuncAttributeMaxDynamicSharedMemorySize,
                         FA_SMEM);

    // ---- hi/lo splits
    const int nX4 = (MROWS * HIDDEN) / 4;
    const int nW4 = (HIDDEN * HIDDEN) / 4;
    split_bf16<<<nX4 / 256, 256>>>(x, xh, xl, nX4);
    split_bf16_w4<<<dim3(nW4 / 256, 4), 256>>>(Wq, Wk, Wv, Wo,
                                               w3h, w3l, woh, wol, nW4);
    concat_bias<<<(3 * HIDDEN) / 256, 256>>>(bq, bk, bv, b3);

    // ---- fused QKV projection -> bf16 hi/lo [B,H,S,D] x3
    const dim3 gQKV(3 * HIDDEN / 128, MROWS / 128, 1);   // (48, 32)
    tgemm_nt<<<gQKV, 256, TG_SMEM>>>(xh, xl, w3h, w3l, b3, HIDDEN, 3 * HIDDEN, 1,
                                     nullptr, qh, ql, kh, kl, vh, vl);

    // ---- fused attention -> AO bf16 hi/lo [B,S,HIDDEN]
    const dim3 gFA(SSEQ / 64, BH, 1);   // (32, 32) = 1024 CTAs
    fa_kernel<<<gFA, 128, FA_SMEM>>>(qh, ql, kh, kl, vh, vl, mask, aoh, aol);

    // ---- output projection (+bias) -> d_out
    const dim3 gO(HIDDEN / 128, MROWS / 128, 1);
    tgemm_nt<<<gO, 256, TG_SMEM>>>(aoh, aol, woh, wol, bo, HIDDEN, HIDDEN, 0,
                                   out, nullptr, nullptr, nullptr, nullptr,
                                   nullptr, nullptr);
}

// round 11
// speedup vs baseline: 1.5235x; 1.5235x over previous
#include <cuda_runtime.h>
#include <cuda_bf16.h>
#include <math.h>
#include <stdint.h>

// Problem constants
#define HIDDEN 2048
#define NHEAD  16
#define HDIM   128
#define BB     2
#define SSEQ   2048
#define BH     (BB * NHEAD)      // 32
#define MROWS  (BB * SSEQ)       // 4096

// ---------------- scratch (device globals; no allocation allowed) -----------
__device__ __align__(128) __nv_bfloat16 g_xh [(size_t)MROWS * HIDDEN];
__device__ __align__(128) __nv_bfloat16 g_xl [(size_t)MROWS * HIDDEN];
__device__ __align__(128) __nv_bfloat16 g_w3h[(size_t)3 * HIDDEN * HIDDEN];  // Wq|Wk|Wv
__device__ __align__(128) __nv_bfloat16 g_w3l[(size_t)3 * HIDDEN * HIDDEN];
__device__ __align__(128) __nv_bfloat16 g_woh[(size_t)HIDDEN * HIDDEN];
__device__ __align__(128) __nv_bfloat16 g_wol[(size_t)HIDDEN * HIDDEN];
__device__ __align__(128) float         g_b3 [3 * HIDDEN];                   // bq|bk|bv
__device__ __align__(128) __nv_bfloat16 g_qh [(size_t)BH * SSEQ * HDIM];  // [B,H,S,D]
__device__ __align__(128) __nv_bfloat16 g_ql [(size_t)BH * SSEQ * HDIM];
__device__ __align__(128) __nv_bfloat16 g_kh [(size_t)BH * SSEQ * HDIM];
__device__ __align__(128) __nv_bfloat16 g_kl [(size_t)BH * SSEQ * HDIM];
__device__ __align__(128) __nv_bfloat16 g_vh [(size_t)BH * SSEQ * HDIM];
__device__ __align__(128) __nv_bfloat16 g_vl [(size_t)BH * SSEQ * HDIM];
__device__ __align__(128) __nv_bfloat16 g_aoh[(size_t)MROWS * HIDDEN];
__device__ __align__(128) __nv_bfloat16 g_aol[(size_t)MROWS * HIDDEN];

// ============================ PTX helpers ====================================
__device__ __forceinline__ uint32_t smem_to_u32(const void* smem_ptr) {
    uint32_t addr;
    asm("{ .reg .u64 tmp; cvta.to.shared.u64 tmp, %1; cvt.u32.u64 %0, tmp; }"
        : "=r"(addr) : "l"(smem_ptr));
    return addr;
}
#define CP_ASYNC16(smem_u32, gptr) \
    asm volatile("cp.async.cg.shared.global [%0], [%1], 16;" \
        :: "r"((uint32_t)(smem_u32)), "l"(gptr) : "memory")
#define CP_ASYNC_COMMIT() asm volatile("cp.async.commit_group;" ::: "memory")
#define CP_ASYNC_WAIT(n)  asm volatile("cp.async.wait_group %0;" :: "n"(n) : "memory")

__device__ __forceinline__ void ldsm4(uint32_t* r, uint32_t addr) {
    asm volatile("ldmatrix.sync.aligned.m8n8.x4.shared.b16 {%0,%1,%2,%3}, [%4];"
        : "=r"(r[0]), "=r"(r[1]), "=r"(r[2]), "=r"(r[3]) : "r"(addr));
}
__device__ __forceinline__ void ldsm4t(uint32_t* r, uint32_t addr) {
    asm volatile("ldmatrix.sync.aligned.m8n8.x4.trans.shared.b16 {%0,%1,%2,%3}, [%4];"
        : "=r"(r[0]), "=r"(r[1]), "=r"(r[2]), "=r"(r[3]) : "r"(addr));
}
__device__ __forceinline__ void mma16816(float* d, const uint32_t* a,
                                         uint32_t b0, uint32_t b1) {
    asm volatile(
        "mma.sync.aligned.m16n8k16.row.col.f32.bf16.bf16.f32 "
        "{%0,%1,%2,%3}, {%4,%5,%6,%7}, {%8,%9}, {%0,%1,%2,%3};"
        : "+f"(d[0]), "+f"(d[1]), "+f"(d[2]), "+f"(d[3])
        : "r"(a[0]), "r"(a[1]), "r"(a[2]), "r"(a[3]), "r"(b0), "r"(b1));
}
__device__ __forceinline__ float fast_exp2(float x) {
    float y;
    asm("ex2.approx.f32 %0, %1;" : "=f"(y) : "f"(x));
    return y;
}

// ===================== HMMA bf16x3 NT GEMM ==================================
// (unchanged: 128x128 CTA, K-chunk 32, XOR swizzle, 3-stage, 1 sync, 2 CTA/SM)
#define TG_TILE     (128 * 64)              // 8192
#define TG_STAGE    (4 * TG_TILE)           // Ah, Al, Bh, Bl = 32768
#define TG_SMEM     (3 * TG_STAGE)          // 98304 -> 2 CTAs/SM

__global__ void __launch_bounds__(256, 2)
tgemm_nt(const __nv_bfloat16* __restrict__ Ah, const __nv_bfloat16* __restrict__ Al,
         const __nv_bfloat16* __restrict__ Bh, const __nv_bfloat16* __restrict__ Bl,
         const float* __restrict__ bias, int K, int Ntot, int mode,
         float* __restrict__ outF,
         __nv_bfloat16* __restrict__ o0h, __nv_bfloat16* __restrict__ o0l,
         __nv_bfloat16* __restrict__ o1h, __nv_bfloat16* __restrict__ o1l,
         __nv_bfloat16* __restrict__ o2h, __nv_bfloat16* __restrict__ o2l)
{
    extern __shared__ __align__(128) char smem[];
    const uint32_t sb = smem_to_u32(smem);

    const int tid  = threadIdx.x;
    const int lane = tid & 31;
    const int wid  = tid >> 5;
    const int wm   = wid >> 2;
    const int wn   = wid & 3;

    const int m0 = blockIdx.y * 128;
    const int n0 = blockIdx.x * 128;
    const int nch = K >> 5;                  // K / 32

    const size_t aBase = (size_t)m0 * K;
    const size_t bBase = (size_t)n0 * K;

    float acc[4][4][4];
    #pragma unroll
    for (int i = 0; i < 4; i++)
        #pragma unroll
        for (int j = 0; j < 4; j++)
            #pragma unroll
            for (int t = 0; t < 4; t++) acc[i][j][t] = 0.0f;

    auto load_chunk = [&](int buf, int k0) {
        const uint32_t tb = sb + buf * TG_STAGE;
        #pragma unroll
        for (int ii = 0; ii < 2; ii++) {
            const int i = tid + ii * 256;        // 0..511
            const int r = i >> 2;                // row 0..127
            const int c = i & 3;                 // 16B chunk 0..3
            const uint32_t so = (uint32_t)(r * 64 + ((c ^ ((r >> 1) & 3)) << 4));
            const size_t aOff = aBase + (size_t)r * K + k0 + c * 8;
            const size_t bOff = bBase + (size_t)r * K + k0 + c * 8;
            CP_ASYNC16(tb + 0 * TG_TILE + so, (const char*)(Ah + aOff));
            CP_ASYNC16(tb + 1 * TG_TILE + so, (const char*)(Al + aOff));
            CP_ASYNC16(tb + 2 * TG_TILE + so, (const char*)(Bh + bOff));
            CP_ASYNC16(tb + 3 * TG_TILE + so, (const char*)(Bl + bOff));
        }
        CP_ASYNC_COMMIT();
    };

    const int hiA = lane >> 4;
    const int swA = ((lane & 15) >> 1) & 3;
    const uint32_t aRowOff = (uint32_t)((wm * 64 + (lane & 15)) * 64);
    const int hiB = (lane >> 3) & 1;
    const int swB = ((lane & 7) >> 1) & 3;
    const uint32_t bRowOff = (uint32_t)((wn * 32 + (lane & 7) + ((lane >> 4) & 1) * 8) * 64);

    load_chunk(0, 0);
    if (nch > 1) load_chunk(1, 32);

    for (int c = 0; c < nch; c++) {
        const int buf = c % 3;
        if (c + 1 < nch) { CP_ASYNC_WAIT(1); } else { CP_ASYNC_WAIT(0); }
        __syncthreads();
        if (c + 2 < nch) load_chunk((c + 2) % 3, (c + 2) * 32);

        const uint32_t tb  = sb + buf * TG_STAGE;
        const uint32_t tAh = tb + 0 * TG_TILE + aRowOff;
        const uint32_t tAl = tb + 1 * TG_TILE + aRowOff;
        const uint32_t tBh = tb + 2 * TG_TILE + bRowOff;
        const uint32_t tBl = tb + 3 * TG_TILE + bRowOff;

        #pragma unroll
        for (int ks = 0; ks < 2; ks++) {
            const uint32_t koA = (uint32_t)(((ks * 2 + hiA) ^ swA) << 4);
            const uint32_t koB = (uint32_t)(((ks * 2 + hiB) ^ swB) << 4);
            uint32_t a[4][4], bh[2][4], bl[2][4];
            #pragma unroll
            for (int mt = 0; mt < 4; mt++) ldsm4(a[mt], tAh + mt * (16 * 64) + koA);
            #pragma unroll
            for (int nt = 0; nt < 2; nt++) {
                ldsm4(bh[nt], tBh + nt * (16 * 64) + koB);
                ldsm4(bl[nt], tBl + nt * (16 * 64) + koB);
            }
            #pragma unroll
            for (int mi = 0; mi < 4; mi++)
                #pragma unroll
                for (int ni = 0; ni < 4; ni++) {
                    const int g = ni >> 1, o = (ni & 1) * 2;
                    mma16816(acc[mi][ni], a[mi], bh[g][o], bh[g][o + 1]);  // Ah*Bh
                    mma16816(acc[mi][ni], a[mi], bl[g][o], bl[g][o + 1]);  // Ah*Bl
                }
            #pragma unroll
            for (int mt = 0; mt < 4; mt++) ldsm4(a[mt], tAl + mt * (16 * 64) + koA);
            #pragma unroll
            for (int mi = 0; mi < 4; mi++)
                #pragma unroll
                for (int ni = 0; ni < 4; ni++) {
                    const int g = ni >> 1, o = (ni & 1) * 2;
                    mma16816(acc[mi][ni], a[mi], bh[g][o], bh[g][o + 1]);  // Al*Bh
                }
        }
    }

    const int gid = lane >> 2;
    const int tig = lane & 3;

    auto storePair = [&](int m, int n, float v0, float v1) {
        if (bias) { v0 += bias[n]; v1 += bias[n + 1]; }
        if (mode == 0) {
            float2 t; t.x = v0; t.y = v1;
            *reinterpret_cast<float2*>(&outF[(size_t)m * Ntot + n]) = t;
        } else {
            __nv_bfloat16 h0 = __float2bfloat16(v0);
            __nv_bfloat16 l0 = __float2bfloat16(v0 - __bfloat162float(h0));
            __nv_bfloat16 h1 = __float2bfloat16(v1);
            __nv_bfloat16 l1 = __float2bfloat16(v1 - __bfloat162float(h1));
            const int p  = n >> 11;                 // 0=q, 1=k, 2=v
            const int n2 = n & (HIDDEN - 1);
            const int b = m >> 11, s = m & (SSEQ - 1);
            const int h = n2 >> 7, d = n2 & (HDIM - 1);
            __nv_bfloat16* oh = (p == 0) ? o0h : ((p == 1) ? o1h : o2h);
            __nv_bfloat16* ol = (p == 0) ? o0l : ((p == 1) ? o1l : o2l);
            const size_t idx = (((size_t)(b * NHEAD + h) * SSEQ) + s) * HDIM + d;
            __nv_bfloat162 th; th.x = h0; th.y = h1;
            __nv_bfloat162 tl; tl.x = l0; tl.y = l1;
            *reinterpret_cast<__nv_bfloat162*>(&oh[idx]) = th;
            *reinterpret_cast<__nv_bfloat162*>(&ol[idx]) = tl;
        }
    };

    #pragma unroll
    for (int mi = 0; mi < 4; mi++) {
        #pragma unroll
        for (int ni = 0; ni < 4; ni++) {
            const int m = m0 + wm * 64 + mi * 16 + gid;
            const int n = n0 + wn * 32 + ni * 8 + tig * 2;
            storePair(m,     n, acc[mi][ni][0], acc[mi][ni][1]);
            storePair(m + 8, n, acc[mi][ni][2], acc[mi][ni][3]);
        }
    }
}

// ===================== fused flash attention (bf16x3) =======================
// 64 q-rows/CTA, 128 thr, 32-key stages, 3 stages, 2 CTAs/SM.
// Software pipeline with ONE loop-carried S buffer (macro SMMA, no lambdas):
//   softmax(c) -> pack P (frees S) -> wait/sync/loads -> SMMA(c+1) into S
//   -> O-rescale -> PV(c).   softmax(c+1) overlaps PV(c) on the tensor queue.
#define FA_STRIDE  272                       // 128 bf16 + 8 pad
#define FA_KVTILE  (32 * FA_STRIDE)          // 8704
#define FA_STAGE   (4 * FA_KVTILE)           // Kh,Kl,Vh,Vl = 34816
#define FA_SMEM    (3 * FA_STAGE)            // 104448 -> 2 CTAs/SM
#define FA_QTILE   (64 * FA_STRIDE)          // 17408

// S = Q @ K(stage at smem addr TB)^T, bf16x3.  Uses S, qA, qL, bOff in scope.
#define FA_SMMA(TB) do {                                                        \
    _Pragma("unroll")                                                           \
    for (int _i = 0; _i < 4; _i++)                                              \
        _Pragma("unroll")                                                       \
        for (int _j = 0; _j < 4; _j++) S[_i][_j] = 0.0f;                        \
    _Pragma("unroll")                                                           \
    for (int _kd = 0; _kd < 8; _kd++) {                                         \
        _Pragma("unroll")                                                       \
        for (int _np = 0; _np < 2; _np++) {                                     \
            uint32_t _bH[4], _bL[4];                                            \
            ldsm4(_bH, (TB) + 0 * FA_KVTILE + bOff + _np * (16 * FA_STRIDE) + _kd * 32); \
            ldsm4(_bL, (TB) + 1 * FA_KVTILE + bOff + _np * (16 * FA_STRIDE) + _kd * 32); \
            mma16816(S[2 * _np],     qA[_kd], _bH[0], _bH[1]);                  \
            mma16816(S[2 * _np],     qL[_kd], _bH[0], _bH[1]);                  \
            mma16816(S[2 * _np],     qA[_kd], _bL[0], _bL[1]);                  \
            mma16816(S[2 * _np + 1], qA[_kd], _bH[2], _bH[3]);                  \
            mma16816(S[2 * _np + 1], qL[_kd], _bH[2], _bH[3]);                  \
            mma16816(S[2 * _np + 1], qA[_kd], _bL[2], _bL[3]);                  \
        }                                                                       \
    }                                                                           \
} while (0)

__global__ void __launch_bounds__(128, 2)
fa_kernel(const __nv_bfloat16* __restrict__ qh, const __nv_bfloat16* __restrict__ ql,
          const __nv_bfloat16* __restrict__ kh, const __nv_bfloat16* __restrict__ kl,
          const __nv_bfloat16* __restrict__ vh, const __nv_bfloat16* __restrict__ vl,
          const float* __restrict__ mask,
          __nv_bfloat16* __restrict__ aoh, __nv_bfloat16* __restrict__ aol)
{
    extern __shared__ __align__(128) char smem[];
    const uint32_t sb   = smem_to_u32(smem);
    const uint32_t sStg = sb;

    const int tid  = threadIdx.x;
    const int lane = tid & 31;
    const int wid  = tid >> 5;           // 0..3
    const int gid  = lane >> 2;
    const int tig  = lane & 3;

    const int z  = blockIdx.y;
    const int q0 = blockIdx.x * 64;
    const int b  = z >> 4;
    const int h  = z & (NHEAD - 1);

    const size_t qBase  = ((size_t)z * SSEQ + q0) * HDIM;
    const size_t kvBase = (size_t)z * SSEQ * HDIM;

    // ---- Q tile (64 rows) staged into stage-2 area, later moved to regs
    const uint32_t sQh = sStg + 2 * FA_STAGE;
    const uint32_t sQl = sQh + FA_QTILE;
    #pragma unroll
    for (int ii = 0; ii < 8; ii++) {
        const int i = tid + ii * 128;
        const int r = i >> 4;
        const int c = i & 15;
        const uint32_t so = (uint32_t)(r * FA_STRIDE + c * 16);
        const size_t go = qBase + (size_t)r * HDIM + c * 8;
        CP_ASYNC16(sQh + so, (const char*)(qh + go));
        CP_ASYNC16(sQl + so, (const char*)(ql + go));
    }
    CP_ASYNC_COMMIT();                       // group: Q

    auto load_k = [&](int st, int k0) {
        const uint32_t tb = sStg + st * FA_STAGE;
        #pragma unroll
        for (int ii = 0; ii < 4; ii++) {
            const int i = tid + ii * 128;
            const int r = i >> 4;
            const int c = i & 15;
            const uint32_t so = (uint32_t)(r * FA_STRIDE + c * 16);
            const size_t go = kvBase + (size_t)(k0 + r) * HDIM + c * 8;
            CP_ASYNC16(tb + 0 * FA_KVTILE + so, (const char*)(kh + go));
            CP_ASYNC16(tb + 1 * FA_KVTILE + so, (const char*)(kl + go));
        }
        CP_ASYNC_COMMIT();
    };
    auto load_v = [&](int st, int k0) {
        const uint32_t tb = sStg + st * FA_STAGE;
        #pragma unroll
        for (int ii = 0; ii < 4; ii++) {
            const int i = tid + ii * 128;
            const int r = i >> 4;
            const int c = i & 15;
            const uint32_t so = (uint32_t)(r * FA_STRIDE + c * 16);
            const size_t go = kvBase + (size_t)(k0 + r) * HDIM + c * 8;
            CP_ASYNC16(tb + 2 * FA_KVTILE + so, (const char*)(vh + go));
            CP_ASYNC16(tb + 3 * FA_KVTILE + so, (const char*)(vl + go));
        }
        CP_ASYNC_COMMIT();
    };
    load_k(0, 0);  load_v(0, 0);             // groups: K0, V0
    load_k(1, 32); load_v(1, 32);            // groups: K1, V1

    // Q fragments -> registers (Q, K0, V0 complete; K1, V1 may pend)
    const uint32_t aOff = (uint32_t)((16 * wid + (lane & 15)) * FA_STRIDE + (lane >> 4) * 16);
    uint32_t qA[8][4], qL[8][4];
    CP_ASYNC_WAIT(2);
    __syncthreads();
    #pragma unroll
    for (int kd = 0; kd < 8; kd++) {
        ldsm4(qA[kd], sQh + aOff + kd * 32);
        ldsm4(qL[kd], sQl + aOff + kd * 32);
    }

    float O[16][4];
    #pragma unroll
    for (int i = 0; i < 16; i++)
        #pragma unroll
        for (int j = 0; j < 4; j++) O[i][j] = 0.0f;
    float m0 = -1e30f, m1 = -1e30f, l0 = 0.0f, l1 = 0.0f;

    const uint32_t bOff = (uint32_t)(((lane & 7) + ((lane >> 4) & 1) * 8) * FA_STRIDE
                                     + ((lane >> 3) & 1) * 16);
    const uint32_t vOff = (uint32_t)(((lane & 7) + ((lane >> 3) & 1) * 8) * FA_STRIDE
                                     + ((lane >> 4) & 1) * 16);
    const float* mrow = mask + (size_t)b * SSEQ;
    const float LOG2E  = 1.4426950408889634f;
    const float scale2 = 0.08838834764831845f * LOG2E;   // (1/sqrt(128))*log2(e)

    // prologue: S(0)  (K0 is complete)
    float S[4][4];
    FA_SMMA(sStg + 0 * FA_STAGE);

    for (int c = 0; c < 64; c++) {
        const int k0 = c * 32;

        // ---- softmax(c): scale + mask (log2 domain)
        #pragma unroll
        for (int nt = 0; nt < 4; nt++) {
            const float2 mv = *reinterpret_cast<const float2*>(mrow + k0 + nt * 8 + 2 * tig);
            const float mx2 = mv.x * LOG2E;
            const float my2 = mv.y * LOG2E;
            S[nt][0] = fmaf(S[nt][0], scale2, mx2);
            S[nt][1] = fmaf(S[nt][1], scale2, my2);
            S[nt][2] = fmaf(S[nt][2], scale2, mx2);
            S[nt][3] = fmaf(S[nt][3], scale2, my2);
        }

        float mx0 = -1e30f, mx1 = -1e30f;
        #pragma unroll
        for (int nt = 0; nt < 4; nt++) {
            mx0 = fmaxf(mx0, fmaxf(S[nt][0], S[nt][1]));
            mx1 = fmaxf(mx1, fmaxf(S[nt][2], S[nt][3]));
        }
        mx0 = fmaxf(mx0, __shfl_xor_sync(0xFFFFFFFFu, mx0, 1));
        mx0 = fmaxf(mx0, __shfl_xor_sync(0xFFFFFFFFu, mx0, 2));
        mx1 = fmaxf(mx1, __shfl_xor_sync(0xFFFFFFFFu, mx1, 1));
        mx1 = fmaxf(mx1, __shfl_xor_sync(0xFFFFFFFFu, mx1, 2));

        const float nm0 = fmaxf(m0, mx0);
        const float nm1 = fmaxf(m1, mx1);
        const float ef0 = fast_exp2(m0 - nm0);
        const float ef1 = fast_exp2(m1 - nm1);

        float rs0 = 0.0f, rs1 = 0.0f;
        #pragma unroll
        for (int nt = 0; nt < 4; nt++) {
            S[nt][0] = fast_exp2(S[nt][0] - nm0);
            S[nt][1] = fast_exp2(S[nt][1] - nm0);
            S[nt][2] = fast_exp2(S[nt][2] - nm1);
            S[nt][3] = fast_exp2(S[nt][3] - nm1);
            rs0 += S[nt][0] + S[nt][1];
            rs1 += S[nt][2] + S[nt][3];
        }
        rs0 += __shfl_xor_sync(0xFFFFFFFFu, rs0, 1);
        rs0 += __shfl_xor_sync(0xFFFFFFFFu, rs0, 2);
        rs1 += __shfl_xor_sync(0xFFFFFFFFu, rs1, 1);
        rs1 += __shfl_xor_sync(0xFFFFFFFFu, rs1, 2);

        l0 = l0 * ef0 + rs0;
        l1 = l1 * ef1 + rs1;
        m0 = nm0; m1 = nm1;

        // ---- pack P (frees S for SMMA(c+1))
        uint32_t paH[2][4], paL[2][4];
        #pragma unroll
        for (int ks = 0; ks < 2; ks++) {
            #pragma unroll
            for (int q = 0; q < 2; q++) {
                #pragma unroll
                for (int rr = 0; rr < 2; rr++) {
                    const float x = S[2 * ks + q][rr * 2 + 0];
                    const float y = S[2 * ks + q][rr * 2 + 1];
                    const __nv_bfloat16 hx = __float2bfloat16(x);
                    const __nv_bfloat16 hy = __float2bfloat16(y);
                    __nv_bfloat162 th; th.x = hx; th.y = hy;
                    __nv_bfloat162 tl;
                    tl.x = __float2bfloat16(x - __bfloat162float(hx));
                    tl.y = __float2bfloat16(y - __bfloat162float(hy));
                    paH[ks][q * 2 + rr] = *reinterpret_cast<uint32_t*>(&th);
                    paL[ks][q * 2 + rr] = *reinterpret_cast<uint32_t*>(&tl);
                }
            }
        }

        // ---- pipeline advance: release V(c)+K(c+1), prefetch stage c+2,
        //      then issue S(c+1) MMAs (covers next softmax's dependency)
        if (c + 1 < 64) {
            CP_ASYNC_WAIT(1);
            __syncthreads();
            if (c + 2 < 64) {
                load_k((c + 2) % 3, (c + 2) * 32);
                load_v((c + 2) % 3, (c + 2) * 32);
            }
            FA_SMMA(sStg + (uint32_t)((c + 1) % 3) * FA_STAGE);
        } else {
            CP_ASYNC_WAIT(0);
            __syncthreads();
        }

        // ---- O rescale (waits on PV(c-1) completion, after SMMA issue)
        #pragma unroll
        for (int nt = 0; nt < 16; nt++) {
            O[nt][0] *= ef0; O[nt][1] *= ef0;
            O[nt][2] *= ef1; O[nt][3] *= ef1;
        }

        // ---- PV(c)
        const uint32_t tb = sStg + (uint32_t)(c % 3) * FA_STAGE;
        #pragma unroll
        for (int ks = 0; ks < 2; ks++) {
            #pragma unroll
            for (int ntp = 0; ntp < 8; ntp++) {
                uint32_t vH[4], vL[4];
                ldsm4t(vH, tb + 2 * FA_KVTILE + vOff + ks * (16 * FA_STRIDE) + ntp * 32);
                ldsm4t(vL, tb + 3 * FA_KVTILE + vOff + ks * (16 * FA_STRIDE) + ntp * 32);
                mma16816(O[2 * ntp],     paH[ks], vH[0], vH[1]);
                mma16816(O[2 * ntp],     paL[ks], vH[0], vH[1]);
                mma16816(O[2 * ntp],     paH[ks], vL[0], vL[1]);
                mma16816(O[2 * ntp + 1], paH[ks], vH[2], vH[3]);
                mma16816(O[2 * ntp + 1], paL[ks], vH[2], vH[3]);
                mma16816(O[2 * ntp + 1], paH[ks], vL[2], vL[3]);
            }
        }
    }

    const float inv0 = 1.0f / l0;
    const float inv1 = 1.0f / l1;
    const int r0 = q0 + 16 * wid + gid;
    const int r1 = r0 + 8;
    #pragma unroll
    for (int nt = 0; nt < 16; nt++) {
        const int d = h * HDIM + nt * 8 + 2 * tig;
        const size_t i0 = ((size_t)b * SSEQ + r0) * HIDDEN + d;
        const size_t i1 = ((size_t)b * SSEQ + r1) * HIDDEN + d;
        const float v00 = O[nt][0] * inv0, v01 = O[nt][1] * inv0;
        const float v10 = O[nt][2] * inv1, v11 = O[nt][3] * inv1;

        const __nv_bfloat16 h00 = __float2bfloat16(v00);
        const __nv_bfloat16 h01 = __float2bfloat16(v01);
        const __nv_bfloat16 h10 = __float2bfloat16(v10);
        const __nv_bfloat16 h11 = __float2bfloat16(v11);
        __nv_bfloat162 th0; th0.x = h00; th0.y = h01;
        __nv_bfloat162 th1; th1.x = h10; th1.y = h11;
        __nv_bfloat162 tl0;
        tl0.x = __float2bfloat16(v00 - __bfloat162float(h00));
        tl0.y = __float2bfloat16(v01 - __bfloat162float(h01));
        __nv_bfloat162 tl1;
        tl1.x = __float2bfloat16(v10 - __bfloat162float(h10));
        tl1.y = __float2bfloat16(v11 - __bfloat162float(h11));
        *reinterpret_cast<__nv_bfloat162*>(&aoh[i0]) = th0;
        *reinterpret_cast<__nv_bfloat162*>(&aol[i0]) = tl0;
        *reinterpret_cast<__nv_bfloat162*>(&aoh[i1]) = th1;
        *reinterpret_cast<__nv_bfloat162*>(&aol[i1]) = tl1;
    }
}

// ===================== fp32 -> bf16 hi/lo split =============================
__global__ void __launch_bounds__(256)
split_bf16(const float* __restrict__ in, __nv_bfloat16* __restrict__ hi,
           __nv_bfloat16* __restrict__ lo, int n4)
{
    const int i = blockIdx.x * 256 + threadIdx.x;
    if (i >= n4) return;
    const float4 v = reinterpret_cast<const float4*>(in)[i];
    union { __nv_bfloat16 b[4]; uint2 u; } H, L;
    H.b[0] = __float2bfloat16(v.x);
    H.b[1] = __float2bfloat16(v.y);
    H.b[2] = __float2bfloat16(v.z);
    H.b[3] = __float2bfloat16(v.w);
    L.b[0] = __float2bfloat16(v.x - __bfloat162float(H.b[0]));
    L.b[1] = __float2bfloat16(v.y - __bfloat162float(H.b[1]));
    L.b[2] = __float2bfloat16(v.z - __bfloat162float(H.b[2]));
    L.b[3] = __float2bfloat16(v.w - __bfloat162float(H.b[3]));
    reinterpret_cast<uint2*>(hi)[i] = H.u;
    reinterpret_cast<uint2*>(lo)[i] = L.u;
}

// 4 weight matrices in one launch: blockIdx.y selects Wq/Wk/Wv/Wo.
__global__ void __launch_bounds__(256)
split_bf16_w4(const float* __restrict__ w0, const float* __restrict__ w1,
              const float* __restrict__ w2, const float* __restrict__ w3,
              __nv_bfloat16* __restrict__ w3h, __nv_bfloat16* __restrict__ w3l,
              __nv_bfloat16* __restrict__ woh, __nv_bfloat16* __restrict__ wol,
              int n4)
{
    const int i = blockIdx.x * 256 + threadIdx.x;
    if (i >= n4) return;
    const int p = blockIdx.y;
    const float* in = (p == 0) ? w0 : (p == 1) ? w1 : (p == 2) ? w2 : w3;
    const size_t wOff = (size_t)HIDDEN * HIDDEN / 4;   // in uint2 units
    __nv_bfloat16* hi;
    __nv_bfloat16* lo;
    size_t o;
    if (p < 3) { hi = w3h; lo = w3l; o = (size_t)p * wOff; }
    else       { hi = woh; lo = wol; o = 0; }

    const float4 v = reinterpret_cast<const float4*>(in)[i];
    union { __nv_bfloat16 b[4]; uint2 u; } H, L;
    H.b[0] = __float2bfloat16(v.x);
    H.b[1] = __float2bfloat16(v.y);
    H.b[2] = __float2bfloat16(v.z);
    H.b[3] = __float2bfloat16(v.w);
    L.b[0] = __float2bfloat16(v.x - __bfloat162float(H.b[0]));
    L.b[1] = __float2bfloat16(v.y - __bfloat162float(H.b[1]));
    L.b[2] = __float2bfloat16(v.z - __bfloat162float(H.b[2]));
    L.b[3] = __float2bfloat16(v.w - __bfloat162float(H.b[3]));
    reinterpret_cast<uint2*>(hi)[o + i] = H.u;
    reinterpret_cast<uint2*>(lo)[o + i] = L.u;
}

// bias concat: [bq | bk | bv]
__global__ void __launch_bounds__(256)
concat_bias(const float* __restrict__ a, const float* __restrict__ b,
            const float* __restrict__ c, float* __restrict__ o)
{
    const int i = blockIdx.x * 256 + threadIdx.x;
    if (i < HIDDEN)          o[i] = a[i];
    else if (i < 2 * HIDDEN) o[i] = b[i - HIDDEN];
    else if (i < 3 * HIDDEN) o[i] = c[i - 2 * HIDDEN];
}

// ---------------------------------------------------------------------------
extern "C" void kernel_launch(void* const* d_in, const int* in_sizes, int n_in,
                              void* d_out, int out_size)
{
    (void)in_sizes; (void)n_in; (void)out_size;
    const float* x    = (const float*)d_in[0];
    const float* mask = (const float*)d_in[1];
    const float* Wq   = (const float*)d_in[2];
    const float* bq   = (const float*)d_in[3];
    const float* Wk   = (const float*)d_in[4];
    const float* bk   = (const float*)d_in[5];
    const float* Wv   = (const float*)d_in[6];
    const float* bv   = (const float*)d_in[7];
    const float* Wo   = (const float*)d_in[8];
    const float* bo   = (const float*)d_in[9];
    float* out = (float*)d_out;

    __nv_bfloat16 *xh, *xl, *w3h, *w3l, *woh, *wol;
    __nv_bfloat16 *qh, *ql, *kh, *kl, *vh, *vl, *aoh, *aol;
    float* b3;
    cudaGetSymbolAddress((void**)&xh,  g_xh);
    cudaGetSymbolAddress((void**)&xl,  g_xl);
    cudaGetSymbolAddress((void**)&w3h, g_w3h);
    cudaGetSymbolAddress((void**)&w3l, g_w3l);
    cudaGetSymbolAddress((void**)&woh, g_woh);
    cudaGetSymbolAddress((void**)&wol, g_wol);
    cudaGetSymbolAddress((void**)&b3,  g_b3);
    cudaGetSymbolAddress((void**)&qh,  g_qh);
    cudaGetSymbolAddress((void**)&ql,  g_ql);
    cudaGetSymbolAddress((void**)&kh,  g_kh);
    cudaGetSymbolAddress((void**)&kl,  g_kl);
    cudaGetSymbolAddress((void**)&vh,  g_vh);
    cudaGetSymbolAddress((void**)&vl,  g_vl);
    cudaGetSymbolAddress((void**)&aoh, g_aoh);
    cudaGetSymbolAddress((void**)&aol, g_aol);

    cudaFuncSetAttribute(tgemm_nt, cudaFuncAttributeMaxDynamicSharedMemorySize,
                         TG_SMEM);
    cudaFuncSetAttribute(fa_kernel, cudaFuncAttributeMaxDynamicSharedMemorySize,
                         FA_SMEM);

    // ---- hi/lo splits
    const int nX4 = (MROWS * HIDDEN) / 4;
    const int nW4 = (HIDDEN * HIDDEN) / 4;
    split_bf16<<<nX4 / 256, 256>>>(x, xh, xl, nX4);
    split_bf16_w4<<<dim3(nW4 / 256, 4), 256>>>(Wq, Wk, Wv, Wo,
                                               w3h, w3l, woh, wol, nW4);
    concat_bias<<<(3 * HIDDEN) / 256, 256>>>(bq, bk, bv, b3);

    // ---- fused QKV projection -> bf16 hi/lo [B,H,S,D] x3
    const dim3 gQKV(3 * HIDDEN / 128, MROWS / 128, 1);   // (48, 32)
    tgemm_nt<<<gQKV, 256, TG_SMEM>>>(xh, xl, w3h, w3l, b3, HIDDEN, 3 * HIDDEN, 1,
                                     nullptr, qh, ql, kh, kl, vh, vl);

    // ---- fused attention -> AO bf16 hi/lo [B,S,HIDDEN]
    const dim3 gFA(SSEQ / 64, BH, 1);   // (32, 32) = 1024 CTAs
    fa_kernel<<<gFA, 128, FA_SMEM>>>(qh, ql, kh, kl, vh, vl, mask, aoh, aol);

    // ---- output projection (+bias) -> d_out
    const dim3 gO(HIDDEN / 128, MROWS / 128, 1);
    tgemm_nt<<<gO, 256, TG_SMEM>>>(aoh, aol, woh, wol, bo, HIDDEN, HIDDEN, 0,
                                   out, nullptr, nullptr, nullptr, nullptr,
                                   nullptr, nullptr);
}